// round 13
// baseline (speedup 1.0000x reference)
#include <cuda_runtime.h>
#include <math.h>
#include <stdint.h>

#define Bc   2
#define Cc   64
#define Hc   192
#define Wc   192
#define Gc   4
#define Cgc  16
#define HW   (Hc*Wc)
#define Nsz  (Bc*HW)          // 73728 pixels total

#define X_ELEMS   ((size_t)Bc*Cc*HW)
#define VPAD 136              // s_val row pitch for 128px tile (136%32==8)
typedef unsigned long long ull;

// Scratch (no allocations allowed)
__device__ float g_modulator[(size_t)Bc*36*HW];
__device__ float g_wt[4*9*16*64];               // deform W [(g*9+k)*16+c][o] tf32
__device__ float g_gsplit[(size_t)Bc*Gc*HW*16]; // [b*4+g][p][16ch]
__device__ float g_owh[288*32];                 // offset conv W hi
__device__ float g_owl[288*32];                 // offset conv W lo
__device__ float g_mwt[576*48];                 // mod conv W tf32

// ---- helpers --------------------------------------------------------------
__device__ __forceinline__ float sigmoidf_(float v) {
    return 1.f / (1.f + expf(-v));
}
__device__ __forceinline__ void cp_async16(void* smem, const void* g) {
    uint32_t s = (uint32_t)__cvta_generic_to_shared(smem);
    asm volatile("cp.async.cg.shared.global [%0], [%1], 16;" :: "r"(s), "l"(g));
}
__device__ __forceinline__ float to_tf32(float x) {
    uint32_t r;
    asm("cvt.rna.tf32.f32 %0, %1;" : "=r"(r) : "f"(x));
    return __uint_as_float(r);
}
__device__ __forceinline__ void mma_tf32(
    float& d0, float& d1, float& d2, float& d3,
    uint32_t a0, uint32_t a1, uint32_t a2, uint32_t a3,
    uint32_t b0, uint32_t b1)
{
    asm volatile(
        "mma.sync.aligned.m16n8k8.row.col.f32.tf32.tf32.f32 "
        "{%0,%1,%2,%3}, {%4,%5,%6,%7}, {%8,%9}, {%0,%1,%2,%3};"
        : "+f"(d0), "+f"(d1), "+f"(d2), "+f"(d3)
        : "r"(a0), "r"(a1), "r"(a2), "r"(a3), "r"(b0), "r"(b1));
}
#define F2U(x) __float_as_uint(x)

// ---------------------------------------------------------------------------
// Kernel 0a: ALL weight transforms merged (73728 elems = 288 blocks).
// ---------------------------------------------------------------------------
__global__ void all_wt_kernel(
    const float* __restrict__ rw,
    const float* __restrict__ ow,
    const float* __restrict__ mw,
    float* __restrict__ wt, float* __restrict__ hi, float* __restrict__ lo,
    float* __restrict__ mwt)
{
    int i = blockIdx.x * 256 + threadIdx.x;
    if (i < 36864) {
        int o = i & 63;
        int r = i >> 6;
        int c = r & 15;
        int r2 = r >> 4;
        int k = r2 % 9, g = r2 / 9;
        wt[i] = to_tf32(rw[(o * 64 + g * 16 + c) * 9 + k]);
    } else if (i < 46080) {
        int i2 = i - 36864;
        int o = i2 & 31;
        int r = i2 >> 5;
        int c = r & 7;
        int r2 = r >> 3;
        int chunk = r2 / 9, t = r2 % 9;
        int ic = (chunk < 2) ? chunk * 8 + c : 16 + (chunk - 2) * 8 + c;
        float v = (o < 18) ? ow[o * 288 + ic * 9 + t] : 0.f;
        float h = to_tf32(v);
        hi[i2] = h;
        lo[i2] = to_tf32(v - h);
    } else {
        int i3 = i - 46080;
        int o = i3 % 48;
        int r = i3 / 48;
        int c = r & 7;
        int r2 = r >> 3;
        int chunk = r2 / 9, t = r2 % 9;
        int ic = chunk * 8 + c;
        float v = (o < 36) ? mw[o * 576 + ic * 9 + t] : 0.f;
        mwt[i3] = to_tf32(v);
    }
}

// ---------------------------------------------------------------------------
// Kernel 0b: NCHW -> group-split transpose: [b][64][HW] -> [b*4+g][HW][16]
// ---------------------------------------------------------------------------
__global__ __launch_bounds__(256) void gsplit_kernel(
    const float* __restrict__ in, float* __restrict__ outp)
{
    __shared__ float t[32][33];
    const int tx = threadIdx.x & 31, ty = threadIdx.x >> 5;
    const int p0 = blockIdx.x * 32;
    const int c0 = blockIdx.y * 32;
    const int b  = blockIdx.z;
#pragma unroll
    for (int j = 0; j < 4; j++) {
        int c = c0 + ty + j * 8;
        t[ty + j * 8][tx] = in[((size_t)(b * Cc + c)) * HW + p0 + tx];
    }
    __syncthreads();
#pragma unroll
    for (int j = 0; j < 4; j++) {
        int p = p0 + ty + j * 8;
        int c = c0 + tx;
        int g = c >> 4, ci = c & 15;
        outp[((size_t)(b * 4 + g) * HW + p) * 16 + ci] = t[tx][ty + j * 8];
    }
}

// ---------------------------------------------------------------------------
// Kernel 1: offset conv via 3xTF32 MMA, A-weights SMEM-staged per chunk.
// ---------------------------------------------------------------------------
__global__ __launch_bounds__(256) void offset_conv_mma(
    const float* __restrict__ wr, const float* __restrict__ src,
    const float* __restrict__ gwh, const float* __restrict__ gwl,
    const float* __restrict__ ob, float* __restrict__ out_off)
{
    __shared__ float s_hi[2720];
    __shared__ float s_lo[2720];
    __shared__ float s_ah[2304];
    __shared__ float s_al[2304];

    const int tid = threadIdx.x;
    const int warp = tid >> 5, lane = tid & 31;
    const int lr = lane >> 2, lc = lane & 3;
    const int x0 = blockIdx.x * 32, y0 = blockIdx.y * 8;
    const int bz = blockIdx.z;
    const int g = bz & 3, b = bz >> 2;

    float d[2][4][4];
#pragma unroll
    for (int mt = 0; mt < 2; mt++)
#pragma unroll
        for (int nt = 0; nt < 4; nt++)
#pragma unroll
            for (int j = 0; j < 4; j++) d[mt][nt][j] = 0.f;

#pragma unroll 1
    for (int chunk = 0; chunk < 4; chunk++) {
        for (int i = tid * 4; i < 2304; i += 1024) {
            cp_async16(&s_ah[i], &gwh[chunk * 2304 + i]);
            cp_async16(&s_al[i], &gwl[chunk * 2304 + i]);
        }
        asm volatile("cp.async.commit_group;" ::: "memory");

        const float* base = (chunk < 2 ? wr : src)
                          + ((size_t)(b * Cc + g * Cgc + (chunk & 1) * 8)) * HW;
        for (int i = tid; i < 2720; i += 256) {
            int c = i / 340, r = i % 340;
            int iy = r / 34, ix = r % 34;
            int gy = y0 - 1 + iy, gx = x0 - 1 + ix;
            float v = 0.f;
            if (gy >= 0 && gy < Hc && gx >= 0 && gx < Wc)
                v = base[(size_t)c * HW + gy * Wc + gx];
            float h = to_tf32(v);
            s_hi[i] = h;
            s_lo[i] = to_tf32(v - h);
        }
        asm volatile("cp.async.wait_group 0;" ::: "memory");
        __syncthreads();

#pragma unroll 1
        for (int t = 0; t < 9; t++) {
            const int kh = t / 3, kw = t % 3;
            const int bb = (warp + kh) * 34 + kw + lr;
            float bh0[4], bh1[4], bl0[4], bl1[4];
#pragma unroll
            for (int nt = 0; nt < 4; nt++) {
                int a = bb + nt * 8;
                bh0[nt] = s_hi[lc * 340 + a];
                bh1[nt] = s_hi[(lc + 4) * 340 + a];
                bl0[nt] = s_lo[lc * 340 + a];
                bl1[nt] = s_lo[(lc + 4) * 340 + a];
            }
            const float* Ah = &s_ah[t * 8 * 32];
            const float* Al = &s_al[t * 8 * 32];
#pragma unroll
            for (int mt = 0; mt < 2; mt++) {
                int m = mt * 16 + lr;
                uint32_t ah0 = F2U(Ah[lc * 32 + m]);
                uint32_t ah1 = F2U(Ah[lc * 32 + m + 8]);
                uint32_t ah2 = F2U(Ah[(lc + 4) * 32 + m]);
                uint32_t ah3 = F2U(Ah[(lc + 4) * 32 + m + 8]);
                uint32_t al0 = F2U(Al[lc * 32 + m]);
                uint32_t al1 = F2U(Al[lc * 32 + m + 8]);
                uint32_t al2 = F2U(Al[(lc + 4) * 32 + m]);
                uint32_t al3 = F2U(Al[(lc + 4) * 32 + m + 8]);
#pragma unroll
                for (int nt = 0; nt < 4; nt++) {
                    mma_tf32(d[mt][nt][0], d[mt][nt][1], d[mt][nt][2], d[mt][nt][3],
                             ah0, ah1, ah2, ah3, F2U(bh0[nt]), F2U(bh1[nt]));
                    mma_tf32(d[mt][nt][0], d[mt][nt][1], d[mt][nt][2], d[mt][nt][3],
                             ah0, ah1, ah2, ah3, F2U(bl0[nt]), F2U(bl1[nt]));
                    mma_tf32(d[mt][nt][0], d[mt][nt][1], d[mt][nt][2], d[mt][nt][3],
                             al0, al1, al2, al3, F2U(bh0[nt]), F2U(bh1[nt]));
                }
            }
        }
        __syncthreads();
    }

    const int yg = y0 + warp;
#pragma unroll
    for (int mt = 0; mt < 2; mt++) {
#pragma unroll
        for (int nt = 0; nt < 4; nt++) {
            int xg = x0 + nt * 8 + 2 * lc;
            int o = mt * 16 + lr;
            if (o < 18) {
                float v0 = 100.f * sigmoidf_(d[mt][nt][0] + ob[o]) - 50.f;
                float v1 = 100.f * sigmoidf_(d[mt][nt][1] + ob[o]) - 50.f;
                *(float2*)&out_off[((size_t)(b * 72 + g * 18 + o)) * HW + yg * Wc + xg]
                    = make_float2(v0, v1);
            }
            int o2 = mt * 16 + lr + 8;
            if (o2 < 18) {
                float v0 = 100.f * sigmoidf_(d[mt][nt][2] + ob[o2]) - 50.f;
                float v1 = 100.f * sigmoidf_(d[mt][nt][3] + ob[o2]) - 50.f;
                *(float2*)&out_off[((size_t)(b * 72 + g * 18 + o2)) * HW + yg * Wc + xg]
                    = make_float2(v0, v1);
            }
        }
    }
}

// ---------------------------------------------------------------------------
// Kernel 2: modulator conv via plain tf32 MMA, A-weights SMEM-staged.
// ---------------------------------------------------------------------------
__global__ __launch_bounds__(256) void mod_conv_mma(
    const float* __restrict__ wr,
    const float* __restrict__ gw, const float* __restrict__ mb,
    float* __restrict__ modout)
{
    __shared__ float s_t[2720];
    __shared__ float s_a[3456];

    const int tid = threadIdx.x;
    const int warp = tid >> 5, lane = tid & 31;
    const int lr = lane >> 2, lc = lane & 3;
    const int x0 = blockIdx.x * 32, y0 = blockIdx.y * 8;
    const int b = blockIdx.z;

    float d[3][4][4];
#pragma unroll
    for (int mt = 0; mt < 3; mt++)
#pragma unroll
        for (int nt = 0; nt < 4; nt++)
#pragma unroll
            for (int j = 0; j < 4; j++) d[mt][nt][j] = 0.f;

#pragma unroll 1
    for (int chunk = 0; chunk < 8; chunk++) {
        for (int i = tid * 4; i < 3456; i += 1024)
            cp_async16(&s_a[i], &gw[chunk * 3456 + i]);
        asm volatile("cp.async.commit_group;" ::: "memory");

        const float* base = wr + ((size_t)(b * Cc + chunk * 8)) * HW;
        for (int i = tid; i < 2720; i += 256) {
            int c = i / 340, r = i % 340;
            int iy = r / 34, ix = r % 34;
            int gy = y0 - 1 + iy, gx = x0 - 1 + ix;
            float v = 0.f;
            if (gy >= 0 && gy < Hc && gx >= 0 && gx < Wc)
                v = base[(size_t)c * HW + gy * Wc + gx];
            s_t[i] = to_tf32(v);
        }
        asm volatile("cp.async.wait_group 0;" ::: "memory");
        __syncthreads();

#pragma unroll 1
        for (int t = 0; t < 9; t++) {
            const int kh = t / 3, kw = t % 3;
            const int bb = (warp + kh) * 34 + kw + lr;
            float b0[4], b1[4];
#pragma unroll
            for (int nt = 0; nt < 4; nt++) {
                int a = bb + nt * 8;
                b0[nt] = s_t[lc * 340 + a];
                b1[nt] = s_t[(lc + 4) * 340 + a];
            }
            const float* Aw = &s_a[t * 8 * 48];
#pragma unroll
            for (int mt = 0; mt < 3; mt++) {
                int m = mt * 16 + lr;
                uint32_t a0 = F2U(Aw[lc * 48 + m]);
                uint32_t a1 = F2U(Aw[lc * 48 + m + 8]);
                uint32_t a2 = F2U(Aw[(lc + 4) * 48 + m]);
                uint32_t a3 = F2U(Aw[(lc + 4) * 48 + m + 8]);
#pragma unroll
                for (int nt = 0; nt < 4; nt++) {
                    mma_tf32(d[mt][nt][0], d[mt][nt][1], d[mt][nt][2], d[mt][nt][3],
                             a0, a1, a2, a3, F2U(b0[nt]), F2U(b1[nt]));
                }
            }
        }
        __syncthreads();
    }

    const int yg = y0 + warp;
#pragma unroll
    for (int mt = 0; mt < 3; mt++) {
#pragma unroll
        for (int nt = 0; nt < 4; nt++) {
            int xg = x0 + nt * 8 + 2 * lc;
            int o = mt * 16 + lr;
            if (o < 36) {
                float v0 = 2.f * sigmoidf_(d[mt][nt][0] + mb[o]);
                float v1 = 2.f * sigmoidf_(d[mt][nt][1] + mb[o]);
                *(float2*)&modout[((size_t)(b * 36 + o)) * HW + yg * Wc + xg]
                    = make_float2(v0, v1);
            }
            int o2 = mt * 16 + lr + 8;
            if (o2 < 36) {
                float v0 = 2.f * sigmoidf_(d[mt][nt][2] + mb[o2]);
                float v1 = 2.f * sigmoidf_(d[mt][nt][3] + mb[o2]);
                *(float2*)&modout[((size_t)(b * 36 + o2)) * HW + yg * Wc + xg]
                    = make_float2(v0, v1);
            }
        }
    }
}

// ---------------------------------------------------------------------------
// Kernel 3: FUSED deform — 128px tile, 3 CTAs/SM for latency hiding.
// Cooperative gather + prefetched offsets + tf32 MMA.
// ---------------------------------------------------------------------------
__global__ __launch_bounds__(256, 3) void deform_fused_kernel(
    const float* __restrict__ gsp,
    const float* __restrict__ off,
    const float* __restrict__ mod,
    const float* __restrict__ gwt,
    float* __restrict__ out_x)
{
    __shared__ float s_val[2][16 * VPAD];
    __shared__ float s_wk[2][16 * 64];
    __shared__ float s_off[2][3 * 128];

    const int tid = threadIdx.x;
    const int warp = tid >> 5, lane = tid & 31;
    const int sub = lane >> 3;
    const int jj = lane & 7;
    const int half = jj >> 2, qq = jj & 3;
    const int blk = blockIdx.x;
    const int b = blk / (HW / 128);
    const int ploc0 = (blk % (HW / 128)) * 128;

    const int wo = warp >> 1;           // 0..3, M-tile (16 outs)
    const int wn = warp & 1;            // 0..1, px half (64)
    const int lr = lane >> 2;
    const int lc = lane & 3;
    const float fhalf = (float)half;

    auto stage_off = [&](int i) {
        const int g = i / 9, k = i % 9;
        if (tid < 96) {
            const int plane = tid >> 5;
            const int t4 = (tid & 31) * 4;
            const float* srcp;
            if (plane == 0)
                srcp = off + (size_t)(b * 72 + g * 18 + 2 * k) * HW + ploc0;
            else if (plane == 1)
                srcp = off + (size_t)(b * 72 + g * 18 + 2 * k + 1) * HW + ploc0;
            else
                srcp = mod + (size_t)(b * 36 + g * 9 + k) * HW + ploc0;
            cp_async16(&s_off[i & 1][plane * 128 + t4], srcp + t4);
        }
    };

    auto stage_w = [&](int i) {
        int flat = tid * 4;
        int c = flat >> 6, o = flat & 63;
        cp_async16(&s_wk[i & 1][c * 64 + o], &gwt[(i * 16 + c) * 64 + o]);
    };

    auto gather = [&](int i) {
        const int buf = i & 1;
        const int g = i / 9, k = i % 9;
        const int kh = k / 3, kw = k % 3;
        const float* gplane = gsp + (size_t)(b * 4 + g) * HW * 16;
        const float* so = s_off[buf];
        float* sv = s_val[buf];

#pragma unroll 4
        for (int s = 0; s < 4; s++) {
            const int pl = warp * 16 + s * 4 + sub;
            const int p = ploc0 + pl;
            const int yy = p / Wc, xx = p % Wc;
            float oy = so[pl];
            float ox = so[128 + pl];
            float m  = so[256 + pl];

            float py = oy + (float)(kh + yy - 1);
            float pxf = ox + (float)(kw + xx - 1);
            float fy = floorf(py), fx = floorf(pxf);
            float ly = py - fy, lx = pxf - fx;
            int y0 = (int)fy, x0 = (int)fx;

            float vx0 = (x0 >= 0 && x0 < Wc) ? 1.f : 0.f;
            float vx1 = (x0 >= -1 && x0 <= Wc - 2) ? 1.f : 0.f;
            float vy0 = (y0 >= 0 && y0 < Hc) ? 1.f : 0.f;
            float vy1 = (y0 >= -1 && y0 <= Hc - 2) ? 1.f : 0.f;

            int rbx = min(max(x0, 0), Wc - 2);
            int cx0 = min(max(x0, 0), Wc - 1);
            int cx1 = min(max(x0 + 1, 0), Wc - 1);
            float s0 = (float)(cx0 - rbx);
            float s1 = (float)(cx1 - rbx);
            float wx0 = (1.f - lx) * vx0;
            float wx1 = lx * vx1;
            float hw = wx0 * (s0 == fhalf ? 1.f : 0.f) + wx1 * (s1 == fhalf ? 1.f : 0.f);

            int ry0 = min(max(y0, 0), Hc - 1);
            int ry1 = min(max(y0 + 1, 0), Hc - 1);
            float a0 = (1.f - ly) * vy0 * m * hw;
            float a1 = ly * vy1 * m * hw;

            const float4* r0p = (const float4*)(gplane + ((size_t)(ry0 * Wc + rbx)) * 16) + jj;
            const float4* r1p = (const float4*)(gplane + ((size_t)(ry1 * Wc + rbx)) * 16) + jj;
            float4 v0 = __ldg(r0p);
            float4 v1 = __ldg(r1p);

            float4 u;
            u.x = v0.x * a0 + v1.x * a1;
            u.y = v0.y * a0 + v1.y * a1;
            u.z = v0.z * a0 + v1.z * a1;
            u.w = v0.w * a0 + v1.w * a1;
            u.x += __shfl_xor_sync(0xFFFFFFFFu, u.x, 4);
            u.y += __shfl_xor_sync(0xFFFFFFFFu, u.y, 4);
            u.z += __shfl_xor_sync(0xFFFFFFFFu, u.z, 4);
            u.w += __shfl_xor_sync(0xFFFFFFFFu, u.w, 4);

            if (half == 0) {
                int cb = qq * 4;
                sv[(cb + 0) * VPAD + pl] = to_tf32(u.x);
                sv[(cb + 1) * VPAD + pl] = to_tf32(u.y);
                sv[(cb + 2) * VPAD + pl] = to_tf32(u.z);
                sv[(cb + 3) * VPAD + pl] = to_tf32(u.w);
            }
        }
    };

    float d[8][4];
#pragma unroll
    for (int nt = 0; nt < 8; nt++)
#pragma unroll
        for (int j = 0; j < 4; j++) d[nt][j] = 0.f;

    stage_off(0);
    stage_off(1);
    stage_w(0);
    asm volatile("cp.async.commit_group;" ::: "memory");
    asm volatile("cp.async.wait_group 0;" ::: "memory");
    __syncthreads();
    gather(0);

#pragma unroll 1
    for (int i = 0; i < 36; i++) {
        asm volatile("cp.async.wait_group 0;" ::: "memory");
        __syncthreads();
        if (i < 35) {
            stage_w(i + 1);
            if (i < 34) stage_off(i + 2);
            asm volatile("cp.async.commit_group;" ::: "memory");
            gather(i + 1);
        }

        const float* sv = s_val[i & 1];
        const float* wk = s_wk[i & 1];
#pragma unroll
        for (int kc = 0; kc < 2; kc++) {
            const int arow = wo * 16 + lr;
            const int ak = kc * 8 + lc;
            uint32_t a0 = __float_as_uint(wk[ak * 64 + arow]);
            uint32_t a1 = __float_as_uint(wk[ak * 64 + arow + 8]);
            uint32_t a2 = __float_as_uint(wk[(ak + 4) * 64 + arow]);
            uint32_t a3 = __float_as_uint(wk[(ak + 4) * 64 + arow + 8]);
#pragma unroll
            for (int nt = 0; nt < 8; nt++) {
                const int n = wn * 64 + nt * 8 + lr;
                const int bk = kc * 8 + lc;
                uint32_t b0 = __float_as_uint(sv[bk * VPAD + n]);
                uint32_t b1 = __float_as_uint(sv[(bk + 4) * VPAD + n]);
                mma_tf32(d[nt][0], d[nt][1], d[nt][2], d[nt][3],
                         a0, a1, a2, a3, b0, b1);
            }
        }
    }

    const int o0 = wo * 16 + lr;
#pragma unroll
    for (int nt = 0; nt < 8; nt++) {
        const size_t p = (size_t)ploc0 + wn * 64 + nt * 8 + 2 * lc;
        *(float2*)&out_x[((size_t)(b * Cc + o0)) * HW + p]     = make_float2(d[nt][0], d[nt][1]);
        *(float2*)&out_x[((size_t)(b * Cc + o0 + 8)) * HW + p] = make_float2(d[nt][2], d[nt][3]);
    }
}

// ---------------------------------------------------------------------------
extern "C" void kernel_launch(void* const* d_in, const int* in_sizes, int n_in,
                              void* d_out, int out_size)
{
    const float* warp_ref = (const float*)d_in[0];
    const float* source   = (const float*)d_in[1];
    const float* offset_w = (const float*)d_in[2];
    const float* offset_b = (const float*)d_in[3];
    const float* mod_w    = (const float*)d_in[4];
    const float* mod_b    = (const float*)d_in[5];
    const float* reg_w    = (const float*)d_in[6];

    float* out_x   = (float*)d_out;             // [B,64,H,W]
    float* out_off = (float*)d_out + X_ELEMS;   // [B,72,H,W]

    float *mod_scratch, *wt_scratch, *gsp_scratch, *owh, *owl, *mwt;
    cudaGetSymbolAddress((void**)&mod_scratch, g_modulator);
    cudaGetSymbolAddress((void**)&wt_scratch, g_wt);
    cudaGetSymbolAddress((void**)&gsp_scratch, g_gsplit);
    cudaGetSymbolAddress((void**)&owh, g_owh);
    cudaGetSymbolAddress((void**)&owl, g_owl);
    cudaGetSymbolAddress((void**)&mwt, g_mwt);

    dim3 blk(256);
    all_wt_kernel<<<288, blk>>>(reg_w, offset_w, mod_w, wt_scratch, owh, owl, mwt);
    gsplit_kernel<<<dim3(HW / 32, 2, Bc), blk>>>(warp_ref, gsp_scratch);
    offset_conv_mma<<<dim3(6, 24, 8), blk>>>(warp_ref, source, owh, owl, offset_b, out_off);
    mod_conv_mma<<<dim3(6, 24, 2), blk>>>(warp_ref, mwt, mod_b, mod_scratch);
    deform_fused_kernel<<<dim3(Nsz / 128), blk>>>(gsp_scratch, out_off, mod_scratch, wt_scratch, out_x);
}

// round 14
// speedup vs baseline: 1.1266x; 1.1266x over previous
#include <cuda_runtime.h>
#include <math.h>
#include <stdint.h>

#define Bc   2
#define Cc   64
#define Hc   192
#define Wc   192
#define Gc   4
#define Cgc  16
#define HW   (Hc*Wc)
#define Nsz  (Bc*HW)          // 73728 pixels total

#define X_ELEMS   ((size_t)Bc*Cc*HW)
#define VPAD 264              // s_val row pitch: conflict-free B frags
typedef unsigned long long ull;

// Scratch (no allocations allowed)
__device__ float g_modulator[(size_t)Bc*36*HW];
__device__ float g_wt[4*9*16*64];               // deform W [(g*9+k)*16+c][o] tf32
__device__ float g_gsplit[(size_t)Bc*Gc*HW*16]; // [b*4+g][p][16ch]
__device__ float g_mwt[576*48];                 // mod conv W tf32

// ---- helpers --------------------------------------------------------------
__device__ __forceinline__ ull ffma2(ull a, ull b, ull c) {
    ull d;
    asm("fma.rn.f32x2 %0, %1, %2, %3;" : "=l"(d) : "l"(a), "l"(b), "l"(c));
    return d;
}
__device__ __forceinline__ ull pack2(float lo, float hi) {
    ull r;
    asm("mov.b64 %0, {%1, %2};" : "=l"(r) : "f"(lo), "f"(hi));
    return r;
}
__device__ __forceinline__ float2 unpack2(ull v) {
    float2 f;
    asm("mov.b64 {%0, %1}, %2;" : "=f"(f.x), "=f"(f.y) : "l"(v));
    return f;
}
__device__ __forceinline__ float sigmoidf_(float v) {
    return 1.f / (1.f + expf(-v));
}
__device__ __forceinline__ void cp_async16(void* smem, const void* g) {
    uint32_t s = (uint32_t)__cvta_generic_to_shared(smem);
    asm volatile("cp.async.cg.shared.global [%0], [%1], 16;" :: "r"(s), "l"(g));
}
__device__ __forceinline__ float to_tf32(float x) {
    uint32_t r;
    asm("cvt.rna.tf32.f32 %0, %1;" : "=r"(r) : "f"(x));
    return __uint_as_float(r);
}
__device__ __forceinline__ void mma_tf32(
    float& d0, float& d1, float& d2, float& d3,
    uint32_t a0, uint32_t a1, uint32_t a2, uint32_t a3,
    uint32_t b0, uint32_t b1)
{
    asm volatile(
        "mma.sync.aligned.m16n8k8.row.col.f32.tf32.tf32.f32 "
        "{%0,%1,%2,%3}, {%4,%5,%6,%7}, {%8,%9}, {%0,%1,%2,%3};"
        : "+f"(d0), "+f"(d1), "+f"(d2), "+f"(d3)
        : "r"(a0), "r"(a1), "r"(a2), "r"(a3), "r"(b0), "r"(b1));
}
#define F2U(x) __float_as_uint(x)

// ---------------------------------------------------------------------------
// Kernel 0a: weight transforms (deform tf32 + mod conv tf32), 252 blocks.
//   [0, 36864)  : deform wt -> g_wt
//   [36864, 64512) : mod conv -> g_mwt
// ---------------------------------------------------------------------------
__global__ void all_wt_kernel(
    const float* __restrict__ rw,
    const float* __restrict__ mw,
    float* __restrict__ wt, float* __restrict__ mwt)
{
    int i = blockIdx.x * 256 + threadIdx.x;
    if (i < 36864) {
        int o = i & 63;
        int r = i >> 6;
        int c = r & 15;
        int r2 = r >> 4;
        int k = r2 % 9, g = r2 / 9;
        wt[i] = to_tf32(rw[(o * 64 + g * 16 + c) * 9 + k]);
    } else if (i < 64512) {
        int i3 = i - 36864;
        int o = i3 % 48;
        int r = i3 / 48;
        int c = r & 7;
        int r2 = r >> 3;
        int chunk = r2 / 9, t = r2 % 9;
        int ic = chunk * 8 + c;
        float v = (o < 36) ? mw[o * 576 + ic * 9 + t] : 0.f;
        mwt[i3] = to_tf32(v);
    }
}

// ---------------------------------------------------------------------------
// Kernel 0b: NCHW -> group-split transpose: [b][64][HW] -> [b*4+g][HW][16]
// ---------------------------------------------------------------------------
__global__ __launch_bounds__(256) void gsplit_kernel(
    const float* __restrict__ in, float* __restrict__ outp)
{
    __shared__ float t[32][33];
    const int tx = threadIdx.x & 31, ty = threadIdx.x >> 5;
    const int p0 = blockIdx.x * 32;
    const int c0 = blockIdx.y * 32;
    const int b  = blockIdx.z;
#pragma unroll
    for (int j = 0; j < 4; j++) {
        int c = c0 + ty + j * 8;
        t[ty + j * 8][tx] = in[((size_t)(b * Cc + c)) * HW + p0 + tx];
    }
    __syncthreads();
#pragma unroll
    for (int j = 0; j < 4; j++) {
        int p = p0 + ty + j * 8;
        int c = c0 + tx;
        int g = c >> 4, ci = c & 15;
        outp[((size_t)(b * 4 + g) * HW + p) * 16 + ci] = t[tx][ty + j * 8];
    }
}

// ---------------------------------------------------------------------------
// Conv bodies for the über kernel (shared SMEM union: 6336 floats)
// ---------------------------------------------------------------------------
__device__ __forceinline__ void offset_conv_body(
    float* sbuf,
    const float* __restrict__ wr, const float* __restrict__ src,
    const float* __restrict__ ow, const float* __restrict__ ob,
    float* __restrict__ out_off, int xb, int yb, int g, int b)
{
    float* s_in = sbuf;          // 4896
    float* s_w  = sbuf + 4896;   // 1440

    const int tid = threadIdx.x;
    const int tx = tid & 31, ty = tid >> 5;
    const int x0 = xb * 32, y0 = yb * 16;

    ull acc[2][9];
#pragma unroll
    for (int p = 0; p < 2; p++)
#pragma unroll
        for (int j = 0; j < 9; j++) acc[p][j] = 0ull;

#pragma unroll 1
    for (int chunk = 0; chunk < 4; chunk++) {
        const float* base = (chunk < 2 ? wr : src)
                          + ((size_t)(b * Cc + g * Cgc + (chunk & 1) * 8)) * HW;
        for (int i = tid; i < 4896; i += 256) {
            int c = i / 612, r = i % 612;
            int iy = r / 34, ix = r % 34;
            int gy = y0 - 1 + iy, gx = x0 - 1 + ix;
            float v = 0.f;
            if (gy >= 0 && gy < Hc && gx >= 0 && gx < Wc)
                v = base[(size_t)c * HW + gy * Wc + gx];
            s_in[i] = v;
        }
        for (int i = tid; i < 1440; i += 256) {
            int o = i % 20;
            int ck = i / 20;
            int k = ck % 9, c = ck / 9;
            s_w[i] = (o < 18) ? ow[(o * 32 + chunk * 8 + c) * 9 + k] : 0.f;
        }
        __syncthreads();

#pragma unroll 2
        for (int c = 0; c < 8; c++) {
#pragma unroll
            for (int t = 0; t < 9; t++) {
                const int kh = t / 3, kw = t % 3;
                const float* wrow = &s_w[(c * 9 + t) * 20];
                ulonglong2 l0 = *(const ulonglong2*)(wrow);
                ulonglong2 l1 = *(const ulonglong2*)(wrow + 4);
                ulonglong2 l2 = *(const ulonglong2*)(wrow + 8);
                ulonglong2 l3 = *(const ulonglong2*)(wrow + 12);
                ull w8 = *(const ull*)(wrow + 16);
#pragma unroll
                for (int p = 0; p < 2; p++) {
                    float v = s_in[c * 612 + (ty + p * 8 + kh) * 34 + tx + kw];
                    ull vv = pack2(v, v);
                    acc[p][0] = ffma2(vv, l0.x, acc[p][0]);
                    acc[p][1] = ffma2(vv, l0.y, acc[p][1]);
                    acc[p][2] = ffma2(vv, l1.x, acc[p][2]);
                    acc[p][3] = ffma2(vv, l1.y, acc[p][3]);
                    acc[p][4] = ffma2(vv, l2.x, acc[p][4]);
                    acc[p][5] = ffma2(vv, l2.y, acc[p][5]);
                    acc[p][6] = ffma2(vv, l3.x, acc[p][6]);
                    acc[p][7] = ffma2(vv, l3.y, acc[p][7]);
                    acc[p][8] = ffma2(vv, w8,  acc[p][8]);
                }
            }
        }
        __syncthreads();
    }

    const int x = x0 + tx;
#pragma unroll
    for (int p = 0; p < 2; p++) {
        int y = y0 + ty + p * 8;
#pragma unroll
        for (int j = 0; j < 9; j++) {
            float2 f = unpack2(acc[p][j]);
            int o0 = 2 * j, o1 = 2 * j + 1;
            float v0 = 100.f * sigmoidf_(f.x + ob[o0]) - 50.f;
            float v1 = 100.f * sigmoidf_(f.y + ob[o1]) - 50.f;
            out_off[((size_t)(b * 72 + g * 18 + o0) * Hc + y) * Wc + x] = v0;
            out_off[((size_t)(b * 72 + g * 18 + o1) * Hc + y) * Wc + x] = v1;
        }
    }
}

__device__ __forceinline__ void mod_conv_mma_body(
    float* sbuf,
    const float* __restrict__ wr,
    const float* __restrict__ gw, const float* __restrict__ mb,
    float* __restrict__ modout, int xb, int yb, int b)
{
    float* s_t = sbuf;           // 2720
    float* s_a = sbuf + 2720;    // 3456

    const int tid = threadIdx.x;
    const int warp = tid >> 5, lane = tid & 31;
    const int lr = lane >> 2, lc = lane & 3;
    const int x0 = xb * 32, y0 = yb * 8;

    float d[3][4][4];
#pragma unroll
    for (int mt = 0; mt < 3; mt++)
#pragma unroll
        for (int nt = 0; nt < 4; nt++)
#pragma unroll
            for (int j = 0; j < 4; j++) d[mt][nt][j] = 0.f;

#pragma unroll 1
    for (int chunk = 0; chunk < 8; chunk++) {
        for (int i = tid * 4; i < 3456; i += 1024)
            cp_async16(&s_a[i], &gw[chunk * 3456 + i]);
        asm volatile("cp.async.commit_group;" ::: "memory");

        const float* base = wr + ((size_t)(b * Cc + chunk * 8)) * HW;
        for (int i = tid; i < 2720; i += 256) {
            int c = i / 340, r = i % 340;
            int iy = r / 34, ix = r % 34;
            int gy = y0 - 1 + iy, gx = x0 - 1 + ix;
            float v = 0.f;
            if (gy >= 0 && gy < Hc && gx >= 0 && gx < Wc)
                v = base[(size_t)c * HW + gy * Wc + gx];
            s_t[i] = to_tf32(v);
        }
        asm volatile("cp.async.wait_group 0;" ::: "memory");
        __syncthreads();

#pragma unroll 1
        for (int t = 0; t < 9; t++) {
            const int kh = t / 3, kw = t % 3;
            const int bb = (warp + kh) * 34 + kw + lr;
            float b0[4], b1[4];
#pragma unroll
            for (int nt = 0; nt < 4; nt++) {
                int a = bb + nt * 8;
                b0[nt] = s_t[lc * 340 + a];
                b1[nt] = s_t[(lc + 4) * 340 + a];
            }
            const float* Aw = &s_a[t * 8 * 48];
#pragma unroll
            for (int mt = 0; mt < 3; mt++) {
                int m = mt * 16 + lr;
                uint32_t a0 = F2U(Aw[lc * 48 + m]);
                uint32_t a1 = F2U(Aw[lc * 48 + m + 8]);
                uint32_t a2 = F2U(Aw[(lc + 4) * 48 + m]);
                uint32_t a3 = F2U(Aw[(lc + 4) * 48 + m + 8]);
#pragma unroll
                for (int nt = 0; nt < 4; nt++) {
                    mma_tf32(d[mt][nt][0], d[mt][nt][1], d[mt][nt][2], d[mt][nt][3],
                             a0, a1, a2, a3, F2U(b0[nt]), F2U(b1[nt]));
                }
            }
        }
        __syncthreads();
    }

    const int yg = y0 + warp;
#pragma unroll
    for (int mt = 0; mt < 3; mt++) {
#pragma unroll
        for (int nt = 0; nt < 4; nt++) {
            int xg = x0 + nt * 8 + 2 * lc;
            int o = mt * 16 + lr;
            if (o < 36) {
                float v0 = 2.f * sigmoidf_(d[mt][nt][0] + mb[o]);
                float v1 = 2.f * sigmoidf_(d[mt][nt][1] + mb[o]);
                *(float2*)&modout[((size_t)(b * 36 + o)) * HW + yg * Wc + xg]
                    = make_float2(v0, v1);
            }
            int o2 = mt * 16 + lr + 8;
            if (o2 < 36) {
                float v0 = 2.f * sigmoidf_(d[mt][nt][2] + mb[o2]);
                float v1 = 2.f * sigmoidf_(d[mt][nt][3] + mb[o2]);
                *(float2*)&modout[((size_t)(b * 36 + o2)) * HW + yg * Wc + xg]
                    = make_float2(v0, v1);
            }
        }
    }
}

// ---------------------------------------------------------------------------
// Kernel 1+2: über conv — 864 CTAs interleaved 2:1 offset(FFMA2):mod(MMA).
// Pipe-complementary co-residency: fma-pipe and tensor-pipe CTAs overlap.
// ---------------------------------------------------------------------------
__global__ __launch_bounds__(256, 2) void uber_conv_kernel(
    const float* __restrict__ wr, const float* __restrict__ src,
    const float* __restrict__ ow, const float* __restrict__ ob,
    const float* __restrict__ mgw, const float* __restrict__ mb,
    float* __restrict__ out_off, float* __restrict__ modout)
{
    __shared__ float sbuf[6336];
    const int i = blockIdx.x;           // 0..863
    const int r = i % 3;
    if (r < 2) {
        int idx = (i / 3) * 2 + r;      // 0..575
        int xb = idx % 6;
        int yb = (idx / 6) % 12;
        int zb = idx / 72;              // 0..7
        offset_conv_body(sbuf, wr, src, ow, ob, out_off, xb, yb, zb & 3, zb >> 2);
    } else {
        int idx = i / 3;                // 0..287
        int xb = idx % 6;
        int yb = (idx / 6) % 24;
        int b = idx / 144;
        mod_conv_mma_body(sbuf, wr, mgw, mb, modout, xb, yb, b);
    }
}

// ---------------------------------------------------------------------------
// Kernel 3: FUSED deform — 256px tile, 2 CTAs/SM, cooperative gather,
// prefetched offsets, tf32 MMA (R12 proven).
// ---------------------------------------------------------------------------
__global__ __launch_bounds__(256, 2) void deform_fused_kernel(
    const float* __restrict__ gsp,
    const float* __restrict__ off,
    const float* __restrict__ mod,
    const float* __restrict__ gwt,
    float* __restrict__ out_x)
{
    __shared__ float s_val[2][16 * VPAD];
    __shared__ float s_wk[2][16 * 64];
    __shared__ float s_off[2][3 * 256];

    const int tid = threadIdx.x;
    const int warp = tid >> 5, lane = tid & 31;
    const int sub = lane >> 3;
    const int jj = lane & 7;
    const int half = jj >> 2, qq = jj & 3;
    const int blk = blockIdx.x;
    const int b = blk / (HW / 256);
    const int ploc0 = (blk % (HW / 256)) * 256;

    const int wo = warp >> 1;
    const int wn = warp & 1;
    const int lr = lane >> 2;
    const int lc = lane & 3;
    const float fhalf = (float)half;

    auto stage_off = [&](int i) {
        const int g = i / 9, k = i % 9;
        const int sec = tid >> 6;
        const int t4 = (tid & 63) * 4;
        if (sec == 0) {
            cp_async16(&s_off[i & 1][t4],
                       off + (size_t)(b * 72 + g * 18 + 2 * k) * HW + ploc0 + t4);
        } else if (sec == 1) {
            cp_async16(&s_off[i & 1][256 + t4],
                       off + (size_t)(b * 72 + g * 18 + 2 * k + 1) * HW + ploc0 + t4);
        } else if (sec == 2) {
            cp_async16(&s_off[i & 1][512 + t4],
                       mod + (size_t)(b * 36 + g * 9 + k) * HW + ploc0 + t4);
        }
    };

    auto stage_w = [&](int i) {
        int flat = tid * 4;
        int c = flat >> 6, o = flat & 63;
        cp_async16(&s_wk[i & 1][c * 64 + o], &gwt[(i * 16 + c) * 64 + o]);
    };

    auto gather = [&](int i) {
        const int buf = i & 1;
        const int g = i / 9, k = i % 9;
        const int kh = k / 3, kw = k % 3;
        const float* gplane = gsp + (size_t)(b * 4 + g) * HW * 16;
        const float* so = s_off[buf];
        float* sv = s_val[buf];

#pragma unroll 4
        for (int s = 0; s < 8; s++) {
            const int pl = warp * 32 + s * 4 + sub;
            const int p = ploc0 + pl;
            const int yy = p / Wc, xx = p % Wc;
            float oy = so[pl];
            float ox = so[256 + pl];
            float m  = so[512 + pl];

            float py = oy + (float)(kh + yy - 1);
            float pxf = ox + (float)(kw + xx - 1);
            float fy = floorf(py), fx = floorf(pxf);
            float ly = py - fy, lx = pxf - fx;
            int y0 = (int)fy, x0 = (int)fx;

            float vx0 = (x0 >= 0 && x0 < Wc) ? 1.f : 0.f;
            float vx1 = (x0 >= -1 && x0 <= Wc - 2) ? 1.f : 0.f;
            float vy0 = (y0 >= 0 && y0 < Hc) ? 1.f : 0.f;
            float vy1 = (y0 >= -1 && y0 <= Hc - 2) ? 1.f : 0.f;

            int rbx = min(max(x0, 0), Wc - 2);
            int cx0 = min(max(x0, 0), Wc - 1);
            int cx1 = min(max(x0 + 1, 0), Wc - 1);
            float s0 = (float)(cx0 - rbx);
            float s1 = (float)(cx1 - rbx);
            float wx0 = (1.f - lx) * vx0;
            float wx1 = lx * vx1;
            float hw = wx0 * (s0 == fhalf ? 1.f : 0.f) + wx1 * (s1 == fhalf ? 1.f : 0.f);

            int ry0 = min(max(y0, 0), Hc - 1);
            int ry1 = min(max(y0 + 1, 0), Hc - 1);
            float a0 = (1.f - ly) * vy0 * m * hw;
            float a1 = ly * vy1 * m * hw;

            const float4* r0p = (const float4*)(gplane + ((size_t)(ry0 * Wc + rbx)) * 16) + jj;
            const float4* r1p = (const float4*)(gplane + ((size_t)(ry1 * Wc + rbx)) * 16) + jj;
            float4 v0 = __ldg(r0p);
            float4 v1 = __ldg(r1p);

            float4 u;
            u.x = v0.x * a0 + v1.x * a1;
            u.y = v0.y * a0 + v1.y * a1;
            u.z = v0.z * a0 + v1.z * a1;
            u.w = v0.w * a0 + v1.w * a1;
            u.x += __shfl_xor_sync(0xFFFFFFFFu, u.x, 4);
            u.y += __shfl_xor_sync(0xFFFFFFFFu, u.y, 4);
            u.z += __shfl_xor_sync(0xFFFFFFFFu, u.z, 4);
            u.w += __shfl_xor_sync(0xFFFFFFFFu, u.w, 4);

            if (half == 0) {
                int cb = qq * 4;
                sv[(cb + 0) * VPAD + pl] = to_tf32(u.x);
                sv[(cb + 1) * VPAD + pl] = to_tf32(u.y);
                sv[(cb + 2) * VPAD + pl] = to_tf32(u.z);
                sv[(cb + 3) * VPAD + pl] = to_tf32(u.w);
            }
        }
    };

    float d[16][4];
#pragma unroll
    for (int nt = 0; nt < 16; nt++)
#pragma unroll
        for (int j = 0; j < 4; j++) d[nt][j] = 0.f;

    stage_off(0);
    stage_off(1);
    stage_w(0);
    asm volatile("cp.async.commit_group;" ::: "memory");
    asm volatile("cp.async.wait_group 0;" ::: "memory");
    __syncthreads();
    gather(0);

#pragma unroll 1
    for (int i = 0; i < 36; i++) {
        asm volatile("cp.async.wait_group 0;" ::: "memory");
        __syncthreads();
        if (i < 35) {
            stage_w(i + 1);
            if (i < 34) stage_off(i + 2);
            asm volatile("cp.async.commit_group;" ::: "memory");
            gather(i + 1);
        }

        const float* sv = s_val[i & 1];
        const float* wk = s_wk[i & 1];
#pragma unroll
        for (int kc = 0; kc < 2; kc++) {
            const int arow = wo * 16 + lr;
            const int ak = kc * 8 + lc;
            uint32_t a0 = __float_as_uint(wk[ak * 64 + arow]);
            uint32_t a1 = __float_as_uint(wk[ak * 64 + arow + 8]);
            uint32_t a2 = __float_as_uint(wk[(ak + 4) * 64 + arow]);
            uint32_t a3 = __float_as_uint(wk[(ak + 4) * 64 + arow + 8]);
#pragma unroll
            for (int nt = 0; nt < 16; nt++) {
                const int n = wn * 128 + nt * 8 + lr;
                const int bk = kc * 8 + lc;
                uint32_t b0 = __float_as_uint(sv[bk * VPAD + n]);
                uint32_t b1 = __float_as_uint(sv[(bk + 4) * VPAD + n]);
                mma_tf32(d[nt][0], d[nt][1], d[nt][2], d[nt][3],
                         a0, a1, a2, a3, b0, b1);
            }
        }
    }

    const int o0 = wo * 16 + lr;
#pragma unroll
    for (int nt = 0; nt < 16; nt++) {
        const size_t p = (size_t)ploc0 + wn * 128 + nt * 8 + 2 * lc;
        *(float2*)&out_x[((size_t)(b * Cc + o0)) * HW + p]     = make_float2(d[nt][0], d[nt][1]);
        *(float2*)&out_x[((size_t)(b * Cc + o0 + 8)) * HW + p] = make_float2(d[nt][2], d[nt][3]);
    }
}

// ---------------------------------------------------------------------------
extern "C" void kernel_launch(void* const* d_in, const int* in_sizes, int n_in,
                              void* d_out, int out_size)
{
    const float* warp_ref = (const float*)d_in[0];
    const float* source   = (const float*)d_in[1];
    const float* offset_w = (const float*)d_in[2];
    const float* offset_b = (const float*)d_in[3];
    const float* mod_w    = (const float*)d_in[4];
    const float* mod_b    = (const float*)d_in[5];
    const float* reg_w    = (const float*)d_in[6];

    float* out_x   = (float*)d_out;             // [B,64,H,W]
    float* out_off = (float*)d_out + X_ELEMS;   // [B,72,H,W]

    float *mod_scratch, *wt_scratch, *gsp_scratch, *mwt;
    cudaGetSymbolAddress((void**)&mod_scratch, g_modulator);
    cudaGetSymbolAddress((void**)&wt_scratch, g_wt);
    cudaGetSymbolAddress((void**)&gsp_scratch, g_gsplit);
    cudaGetSymbolAddress((void**)&mwt, g_mwt);

    dim3 blk(256);
    all_wt_kernel<<<252, blk>>>(reg_w, mod_w, wt_scratch, mwt);
    gsplit_kernel<<<dim3(HW / 32, 2, Bc), blk>>>(warp_ref, gsp_scratch);
    uber_conv_kernel<<<864, blk>>>(warp_ref, source, offset_w, offset_b,
                                   mwt, mod_b, out_off, mod_scratch);
    deform_fused_kernel<<<dim3(Nsz / 256), blk>>>(gsp_scratch, out_off, mod_scratch, wt_scratch, out_x);
}

// round 15
// speedup vs baseline: 1.3101x; 1.1629x over previous
#include <cuda_runtime.h>
#include <math.h>
#include <stdint.h>

#define Bc   2
#define Cc   64
#define Hc   192
#define Wc   192
#define Gc   4
#define Cgc  16
#define HW   (Hc*Wc)
#define Nsz  (Bc*HW)          // 73728 pixels total

#define X_ELEMS   ((size_t)Bc*Cc*HW)
#define VPAD 264              // s_val row pitch: conflict-free (264%32==8)
typedef unsigned long long ull;

// Scratch (no allocations allowed)
__device__ float g_modulator[(size_t)Bc*36*HW];
__device__ float g_wt[4*9*16*64];               // deform W [(g*9+k)*16+c][o] tf32
__device__ float g_gsplit[(size_t)Bc*Gc*HW*16]; // [b*4+g][p][16ch]
__device__ float g_mwt[576*48];                 // mod conv W tf32

// ---- helpers --------------------------------------------------------------
__device__ __forceinline__ ull ffma2(ull a, ull b, ull c) {
    ull d;
    asm("fma.rn.f32x2 %0, %1, %2, %3;" : "=l"(d) : "l"(a), "l"(b), "l"(c));
    return d;
}
__device__ __forceinline__ ull pack2(float lo, float hi) {
    ull r;
    asm("mov.b64 %0, {%1, %2};" : "=l"(r) : "f"(lo), "f"(hi));
    return r;
}
__device__ __forceinline__ float2 unpack2(ull v) {
    float2 f;
    asm("mov.b64 {%0, %1}, %2;" : "=f"(f.x), "=f"(f.y) : "l"(v));
    return f;
}
__device__ __forceinline__ float sigmoidf_(float v) {
    return 1.f / (1.f + expf(-v));
}
__device__ __forceinline__ void cp_async16(void* smem, const void* g) {
    uint32_t s = (uint32_t)__cvta_generic_to_shared(smem);
    asm volatile("cp.async.cg.shared.global [%0], [%1], 16;" :: "r"(s), "l"(g));
}
__device__ __forceinline__ float to_tf32(float x) {
    uint32_t r;
    asm("cvt.rna.tf32.f32 %0, %1;" : "=r"(r) : "f"(x));
    return __uint_as_float(r);
}
__device__ __forceinline__ void mma_tf32(
    float& d0, float& d1, float& d2, float& d3,
    uint32_t a0, uint32_t a1, uint32_t a2, uint32_t a3,
    uint32_t b0, uint32_t b1)
{
    asm volatile(
        "mma.sync.aligned.m16n8k8.row.col.f32.tf32.tf32.f32 "
        "{%0,%1,%2,%3}, {%4,%5,%6,%7}, {%8,%9}, {%0,%1,%2,%3};"
        : "+f"(d0), "+f"(d1), "+f"(d2), "+f"(d3)
        : "r"(a0), "r"(a1), "r"(a2), "r"(a3), "r"(b0), "r"(b1));
}
#define F2U(x) __float_as_uint(x)

// ---------------------------------------------------------------------------
// Kernel 0a: weight transforms (deform tf32 + mod conv tf32), 252 blocks.
// ---------------------------------------------------------------------------
__global__ void all_wt_kernel(
    const float* __restrict__ rw,
    const float* __restrict__ mw,
    float* __restrict__ wt, float* __restrict__ mwt)
{
    int i = blockIdx.x * 256 + threadIdx.x;
    if (i < 36864) {
        int o = i & 63;
        int r = i >> 6;
        int c = r & 15;
        int r2 = r >> 4;
        int k = r2 % 9, g = r2 / 9;
        wt[i] = to_tf32(rw[(o * 64 + g * 16 + c) * 9 + k]);
    } else if (i < 64512) {
        int i3 = i - 36864;
        int o = i3 % 48;
        int r = i3 / 48;
        int c = r & 7;
        int r2 = r >> 3;
        int chunk = r2 / 9, t = r2 % 9;
        int ic = chunk * 8 + c;
        float v = (o < 36) ? mw[o * 576 + ic * 9 + t] : 0.f;
        mwt[i3] = to_tf32(v);
    }
}

// ---------------------------------------------------------------------------
// Kernel 0b: NCHW -> group-split transpose: [b][64][HW] -> [b*4+g][HW][16]
// ---------------------------------------------------------------------------
__global__ __launch_bounds__(256) void gsplit_kernel(
    const float* __restrict__ in, float* __restrict__ outp)
{
    __shared__ float t[32][33];
    const int tx = threadIdx.x & 31, ty = threadIdx.x >> 5;
    const int p0 = blockIdx.x * 32;
    const int c0 = blockIdx.y * 32;
    const int b  = blockIdx.z;
#pragma unroll
    for (int j = 0; j < 4; j++) {
        int c = c0 + ty + j * 8;
        t[ty + j * 8][tx] = in[((size_t)(b * Cc + c)) * HW + p0 + tx];
    }
    __syncthreads();
#pragma unroll
    for (int j = 0; j < 4; j++) {
        int p = p0 + ty + j * 8;
        int c = c0 + tx;
        int g = c >> 4, ci = c & 15;
        outp[((size_t)(b * 4 + g) * HW + p) * 16 + ci] = t[tx][ty + j * 8];
    }
}

// ---------------------------------------------------------------------------
// Conv bodies for the über kernel (shared SMEM union: 6336 floats)
// ---------------------------------------------------------------------------
__device__ __forceinline__ void offset_conv_body(
    float* sbuf,
    const float* __restrict__ wr, const float* __restrict__ src,
    const float* __restrict__ ow, const float* __restrict__ ob,
    float* __restrict__ out_off, int xb, int yb, int g, int b)
{
    float* s_in = sbuf;          // 4896
    float* s_w  = sbuf + 4896;   // 1440

    const int tid = threadIdx.x;
    const int tx = tid & 31, ty = tid >> 5;
    const int x0 = xb * 32, y0 = yb * 16;

    ull acc[2][9];
#pragma unroll
    for (int p = 0; p < 2; p++)
#pragma unroll
        for (int j = 0; j < 9; j++) acc[p][j] = 0ull;

#pragma unroll 1
    for (int chunk = 0; chunk < 4; chunk++) {
        const float* base = (chunk < 2 ? wr : src)
                          + ((size_t)(b * Cc + g * Cgc + (chunk & 1) * 8)) * HW;
        for (int i = tid; i < 4896; i += 256) {
            int c = i / 612, r = i % 612;
            int iy = r / 34, ix = r % 34;
            int gy = y0 - 1 + iy, gx = x0 - 1 + ix;
            float v = 0.f;
            if (gy >= 0 && gy < Hc && gx >= 0 && gx < Wc)
                v = base[(size_t)c * HW + gy * Wc + gx];
            s_in[i] = v;
        }
        for (int i = tid; i < 1440; i += 256) {
            int o = i % 20;
            int ck = i / 20;
            int k = ck % 9, c = ck / 9;
            s_w[i] = (o < 18) ? ow[(o * 32 + chunk * 8 + c) * 9 + k] : 0.f;
        }
        __syncthreads();

#pragma unroll 2
        for (int c = 0; c < 8; c++) {
#pragma unroll
            for (int t = 0; t < 9; t++) {
                const int kh = t / 3, kw = t % 3;
                const float* wrow = &s_w[(c * 9 + t) * 20];
                ulonglong2 l0 = *(const ulonglong2*)(wrow);
                ulonglong2 l1 = *(const ulonglong2*)(wrow + 4);
                ulonglong2 l2 = *(const ulonglong2*)(wrow + 8);
                ulonglong2 l3 = *(const ulonglong2*)(wrow + 12);
                ull w8 = *(const ull*)(wrow + 16);
#pragma unroll
                for (int p = 0; p < 2; p++) {
                    float v = s_in[c * 612 + (ty + p * 8 + kh) * 34 + tx + kw];
                    ull vv = pack2(v, v);
                    acc[p][0] = ffma2(vv, l0.x, acc[p][0]);
                    acc[p][1] = ffma2(vv, l0.y, acc[p][1]);
                    acc[p][2] = ffma2(vv, l1.x, acc[p][2]);
                    acc[p][3] = ffma2(vv, l1.y, acc[p][3]);
                    acc[p][4] = ffma2(vv, l2.x, acc[p][4]);
                    acc[p][5] = ffma2(vv, l2.y, acc[p][5]);
                    acc[p][6] = ffma2(vv, l3.x, acc[p][6]);
                    acc[p][7] = ffma2(vv, l3.y, acc[p][7]);
                    acc[p][8] = ffma2(vv, w8,  acc[p][8]);
                }
            }
        }
        __syncthreads();
    }

    const int x = x0 + tx;
#pragma unroll
    for (int p = 0; p < 2; p++) {
        int y = y0 + ty + p * 8;
#pragma unroll
        for (int j = 0; j < 9; j++) {
            float2 f = unpack2(acc[p][j]);
            int o0 = 2 * j, o1 = 2 * j + 1;
            float v0 = 100.f * sigmoidf_(f.x + ob[o0]) - 50.f;
            float v1 = 100.f * sigmoidf_(f.y + ob[o1]) - 50.f;
            out_off[((size_t)(b * 72 + g * 18 + o0) * Hc + y) * Wc + x] = v0;
            out_off[((size_t)(b * 72 + g * 18 + o1) * Hc + y) * Wc + x] = v1;
        }
    }
}

__device__ __forceinline__ void mod_conv_mma_body(
    float* sbuf,
    const float* __restrict__ wr,
    const float* __restrict__ gw, const float* __restrict__ mb,
    float* __restrict__ modout, int xb, int yb, int b)
{
    float* s_t = sbuf;           // 2720
    float* s_a = sbuf + 2720;    // 3456

    const int tid = threadIdx.x;
    const int warp = tid >> 5, lane = tid & 31;
    const int lr = lane >> 2, lc = lane & 3;
    const int x0 = xb * 32, y0 = yb * 8;

    float d[3][4][4];
#pragma unroll
    for (int mt = 0; mt < 3; mt++)
#pragma unroll
        for (int nt = 0; nt < 4; nt++)
#pragma unroll
            for (int j = 0; j < 4; j++) d[mt][nt][j] = 0.f;

#pragma unroll 1
    for (int chunk = 0; chunk < 8; chunk++) {
        for (int i = tid * 4; i < 3456; i += 1024)
            cp_async16(&s_a[i], &gw[chunk * 3456 + i]);
        asm volatile("cp.async.commit_group;" ::: "memory");

        const float* base = wr + ((size_t)(b * Cc + chunk * 8)) * HW;
        for (int i = tid; i < 2720; i += 256) {
            int c = i / 340, r = i % 340;
            int iy = r / 34, ix = r % 34;
            int gy = y0 - 1 + iy, gx = x0 - 1 + ix;
            float v = 0.f;
            if (gy >= 0 && gy < Hc && gx >= 0 && gx < Wc)
                v = base[(size_t)c * HW + gy * Wc + gx];
            s_t[i] = to_tf32(v);
        }
        asm volatile("cp.async.wait_group 0;" ::: "memory");
        __syncthreads();

#pragma unroll 1
        for (int t = 0; t < 9; t++) {
            const int kh = t / 3, kw = t % 3;
            const int bb = (warp + kh) * 34 + kw + lr;
            float b0[4], b1[4];
#pragma unroll
            for (int nt = 0; nt < 4; nt++) {
                int a = bb + nt * 8;
                b0[nt] = s_t[lc * 340 + a];
                b1[nt] = s_t[(lc + 4) * 340 + a];
            }
            const float* Aw = &s_a[t * 8 * 48];
#pragma unroll
            for (int mt = 0; mt < 3; mt++) {
                int m = mt * 16 + lr;
                uint32_t a0 = F2U(Aw[lc * 48 + m]);
                uint32_t a1 = F2U(Aw[lc * 48 + m + 8]);
                uint32_t a2 = F2U(Aw[(lc + 4) * 48 + m]);
                uint32_t a3 = F2U(Aw[(lc + 4) * 48 + m + 8]);
#pragma unroll
                for (int nt = 0; nt < 4; nt++) {
                    mma_tf32(d[mt][nt][0], d[mt][nt][1], d[mt][nt][2], d[mt][nt][3],
                             a0, a1, a2, a3, F2U(b0[nt]), F2U(b1[nt]));
                }
            }
        }
        __syncthreads();
    }

    const int yg = y0 + warp;
#pragma unroll
    for (int mt = 0; mt < 3; mt++) {
#pragma unroll
        for (int nt = 0; nt < 4; nt++) {
            int xg = x0 + nt * 8 + 2 * lc;
            int o = mt * 16 + lr;
            if (o < 36) {
                float v0 = 2.f * sigmoidf_(d[mt][nt][0] + mb[o]);
                float v1 = 2.f * sigmoidf_(d[mt][nt][1] + mb[o]);
                *(float2*)&modout[((size_t)(b * 36 + o)) * HW + yg * Wc + xg]
                    = make_float2(v0, v1);
            }
            int o2 = mt * 16 + lr + 8;
            if (o2 < 36) {
                float v0 = 2.f * sigmoidf_(d[mt][nt][2] + mb[o2]);
                float v1 = 2.f * sigmoidf_(d[mt][nt][3] + mb[o2]);
                *(float2*)&modout[((size_t)(b * 36 + o2)) * HW + yg * Wc + xg]
                    = make_float2(v0, v1);
            }
        }
    }
}

// ---------------------------------------------------------------------------
// Kernel 1+2: über conv — 864 CTAs interleaved 2:1 offset(FFMA2):mod(MMA).
// ---------------------------------------------------------------------------
__global__ __launch_bounds__(256, 2) void uber_conv_kernel(
    const float* __restrict__ wr, const float* __restrict__ src,
    const float* __restrict__ ow, const float* __restrict__ ob,
    const float* __restrict__ mgw, const float* __restrict__ mb,
    float* __restrict__ out_off, float* __restrict__ modout)
{
    __shared__ float sbuf[6336];
    const int i = blockIdx.x;
    const int r = i % 3;
    if (r < 2) {
        int idx = (i / 3) * 2 + r;
        int xb = idx % 6;
        int yb = (idx / 6) % 12;
        int zb = idx / 72;
        offset_conv_body(sbuf, wr, src, ow, ob, out_off, xb, yb, zb & 3, zb >> 2);
    } else {
        int idx = i / 3;
        int xb = idx % 6;
        int yb = (idx / 6) % 24;
        int b = idx / 144;
        mod_conv_mma_body(sbuf, wr, mgw, mb, modout, xb, yb, b);
    }
}

// ---------------------------------------------------------------------------
// Kernel 3: FUSED deform — NEW gather: 4 lanes/pixel (lane = channel quad),
// per-lane 4-corner bilinear (no shfl, no predicated STS, half the s-steps).
// Prefetched offsets + tf32 MMA unchanged.
// ---------------------------------------------------------------------------
__global__ __launch_bounds__(256, 2) void deform_fused_kernel(
    const float* __restrict__ gsp,
    const float* __restrict__ off,
    const float* __restrict__ mod,
    const float* __restrict__ gwt,
    float* __restrict__ out_x)
{
    __shared__ float s_val[2][16 * VPAD];
    __shared__ float s_wk[2][16 * 64];
    __shared__ float s_off[2][3 * 256];

    const int tid = threadIdx.x;
    const int warp = tid >> 5, lane = tid & 31;
    const int px8 = lane >> 2;          // pixel within 8-px step
    const int qq = lane & 3;            // channel quad
    const int blk = blockIdx.x;
    const int b = blk / (HW / 256);
    const int ploc0 = (blk % (HW / 256)) * 256;

    const int wo = warp >> 1;
    const int wn = warp & 1;
    const int lr = lane >> 2;
    const int lc = lane & 3;

    auto stage_off = [&](int i) {
        const int g = i / 9, k = i % 9;
        const int sec = tid >> 6;
        const int t4 = (tid & 63) * 4;
        if (sec == 0) {
            cp_async16(&s_off[i & 1][t4],
                       off + (size_t)(b * 72 + g * 18 + 2 * k) * HW + ploc0 + t4);
        } else if (sec == 1) {
            cp_async16(&s_off[i & 1][256 + t4],
                       off + (size_t)(b * 72 + g * 18 + 2 * k + 1) * HW + ploc0 + t4);
        } else if (sec == 2) {
            cp_async16(&s_off[i & 1][512 + t4],
                       mod + (size_t)(b * 36 + g * 9 + k) * HW + ploc0 + t4);
        }
    };

    auto stage_w = [&](int i) {
        int flat = tid * 4;
        int c = flat >> 6, o = flat & 63;
        cp_async16(&s_wk[i & 1][c * 64 + o], &gwt[(i * 16 + c) * 64 + o]);
    };

    auto gather = [&](int i) {
        const int buf = i & 1;
        const int g = i / 9, k = i % 9;
        const int kh = k / 3, kw = k % 3;
        const float* gplane = gsp + (size_t)(b * 4 + g) * HW * 16 + qq * 4;
        const float* so = s_off[buf];
        float* sv = s_val[buf];

#pragma unroll
        for (int s = 0; s < 4; s++) {
            const int pl = warp * 32 + s * 8 + px8;
            const int p = ploc0 + pl;
            const int yy = p / Wc, xx = p % Wc;
            float oy = so[pl];
            float ox = so[256 + pl];
            float m  = so[512 + pl];

            float py = oy + (float)(kh + yy - 1);
            float pxf = ox + (float)(kw + xx - 1);
            float fy = floorf(py), fx = floorf(pxf);
            float ly = py - fy, lx = pxf - fx;
            int y0 = (int)fy, x0 = (int)fx;

            float vy0 = (y0 >= 0 && y0 < Hc) ? 1.f : 0.f;
            float vy1 = (y0 >= -1 && y0 <= Hc - 2) ? 1.f : 0.f;
            float vx0 = (x0 >= 0 && x0 < Wc) ? 1.f : 0.f;
            float vx1 = (x0 >= -1 && x0 <= Wc - 2) ? 1.f : 0.f;

            int ry0 = min(max(y0, 0), Hc - 1);
            int ry1 = min(max(y0 + 1, 0), Hc - 1);
            int cx0 = min(max(x0, 0), Wc - 1);
            int cx1 = min(max(x0 + 1, 0), Wc - 1);

            float w00 = (1.f - ly) * (1.f - lx) * m * vy0 * vx0;
            float w01 = (1.f - ly) * lx * m * vy0 * vx1;
            float w10 = ly * (1.f - lx) * m * vy1 * vx0;
            float w11 = ly * lx * m * vy1 * vx1;

            float4 c00 = __ldg((const float4*)(gplane + ((size_t)(ry0 * Wc + cx0)) * 16));
            float4 c01 = __ldg((const float4*)(gplane + ((size_t)(ry0 * Wc + cx1)) * 16));
            float4 c10 = __ldg((const float4*)(gplane + ((size_t)(ry1 * Wc + cx0)) * 16));
            float4 c11 = __ldg((const float4*)(gplane + ((size_t)(ry1 * Wc + cx1)) * 16));

            float u0 = w00 * c00.x + w01 * c01.x + w10 * c10.x + w11 * c11.x;
            float u1 = w00 * c00.y + w01 * c01.y + w10 * c10.y + w11 * c11.y;
            float u2 = w00 * c00.z + w01 * c01.z + w10 * c10.z + w11 * c11.z;
            float u3 = w00 * c00.w + w01 * c01.w + w10 * c10.w + w11 * c11.w;

            const int cb = qq * 4;
            sv[(cb + 0) * VPAD + pl] = to_tf32(u0);
            sv[(cb + 1) * VPAD + pl] = to_tf32(u1);
            sv[(cb + 2) * VPAD + pl] = to_tf32(u2);
            sv[(cb + 3) * VPAD + pl] = to_tf32(u3);
        }
    };

    float d[16][4];
#pragma unroll
    for (int nt = 0; nt < 16; nt++)
#pragma unroll
        for (int j = 0; j < 4; j++) d[nt][j] = 0.f;

    stage_off(0);
    stage_off(1);
    stage_w(0);
    asm volatile("cp.async.commit_group;" ::: "memory");
    asm volatile("cp.async.wait_group 0;" ::: "memory");
    __syncthreads();
    gather(0);

#pragma unroll 1
    for (int i = 0; i < 36; i++) {
        asm volatile("cp.async.wait_group 0;" ::: "memory");
        __syncthreads();
        if (i < 35) {
            stage_w(i + 1);
            if (i < 34) stage_off(i + 2);
            asm volatile("cp.async.commit_group;" ::: "memory");
            gather(i + 1);
        }

        const float* sv = s_val[i & 1];
        const float* wk = s_wk[i & 1];
#pragma unroll
        for (int kc = 0; kc < 2; kc++) {
            const int arow = wo * 16 + lr;
            const int ak = kc * 8 + lc;
            uint32_t a0 = __float_as_uint(wk[ak * 64 + arow]);
            uint32_t a1 = __float_as_uint(wk[ak * 64 + arow + 8]);
            uint32_t a2 = __float_as_uint(wk[(ak + 4) * 64 + arow]);
            uint32_t a3 = __float_as_uint(wk[(ak + 4) * 64 + arow + 8]);
#pragma unroll
            for (int nt = 0; nt < 16; nt++) {
                const int n = wn * 128 + nt * 8 + lr;
                const int bk = kc * 8 + lc;
                uint32_t b0 = __float_as_uint(sv[bk * VPAD + n]);
                uint32_t b1 = __float_as_uint(sv[(bk + 4) * VPAD + n]);
                mma_tf32(d[nt][0], d[nt][1], d[nt][2], d[nt][3],
                         a0, a1, a2, a3, b0, b1);
            }
        }
    }

    const int o0 = wo * 16 + lr;
#pragma unroll
    for (int nt = 0; nt < 16; nt++) {
        const size_t p = (size_t)ploc0 + wn * 128 + nt * 8 + 2 * lc;
        *(float2*)&out_x[((size_t)(b * Cc + o0)) * HW + p]     = make_float2(d[nt][0], d[nt][1]);
        *(float2*)&out_x[((size_t)(b * Cc + o0 + 8)) * HW + p] = make_float2(d[nt][2], d[nt][3]);
    }
}

// ---------------------------------------------------------------------------
extern "C" void kernel_launch(void* const* d_in, const int* in_sizes, int n_in,
                              void* d_out, int out_size)
{
    const float* warp_ref = (const float*)d_in[0];
    const float* source   = (const float*)d_in[1];
    const float* offset_w = (const float*)d_in[2];
    const float* offset_b = (const float*)d_in[3];
    const float* mod_w    = (const float*)d_in[4];
    const float* mod_b    = (const float*)d_in[5];
    const float* reg_w    = (const float*)d_in[6];

    float* out_x   = (float*)d_out;             // [B,64,H,W]
    float* out_off = (float*)d_out + X_ELEMS;   // [B,72,H,W]

    float *mod_scratch, *wt_scratch, *gsp_scratch, *mwt;
    cudaGetSymbolAddress((void**)&mod_scratch, g_modulator);
    cudaGetSymbolAddress((void**)&wt_scratch, g_wt);
    cudaGetSymbolAddress((void**)&gsp_scratch, g_gsplit);
    cudaGetSymbolAddress((void**)&mwt, g_mwt);

    dim3 blk(256);
    all_wt_kernel<<<252, blk>>>(reg_w, mod_w, wt_scratch, mwt);
    gsplit_kernel<<<dim3(HW / 32, 2, Bc), blk>>>(warp_ref, gsp_scratch);
    uber_conv_kernel<<<864, blk>>>(warp_ref, source, offset_w, offset_b,
                                   mwt, mod_b, out_off, mod_scratch);
    deform_fused_kernel<<<dim3(Nsz / 256), blk>>>(gsp_scratch, out_off, mod_scratch, wt_scratch, out_x);
}

// round 16
// speedup vs baseline: 1.3550x; 1.0342x over previous
#include <cuda_runtime.h>
#include <math.h>
#include <stdint.h>

#define Bc   2
#define Cc   64
#define Hc   192
#define Wc   192
#define Gc   4
#define Cgc  16
#define HW   (Hc*Wc)
#define Nsz  (Bc*HW)          // 73728 pixels total

#define X_ELEMS   ((size_t)Bc*Cc*HW)
#define VPAD 264              // s_val row pitch (264%32==8)
typedef unsigned long long ull;

// Scratch (no allocations allowed)
__device__ float g_modulator[(size_t)Bc*36*HW];
__device__ float g_wt[4*9*16*64];               // deform W [(g*9+k)*16+rho(c)][o] tf32
__device__ float g_gsplit[(size_t)Bc*Gc*HW*16]; // [b*4+g][p][16ch]
__device__ float g_mwt[576*48];                 // mod conv W tf32

// ---- helpers --------------------------------------------------------------
__device__ __forceinline__ ull ffma2(ull a, ull b, ull c) {
    ull d;
    asm("fma.rn.f32x2 %0, %1, %2, %3;" : "=l"(d) : "l"(a), "l"(b), "l"(c));
    return d;
}
__device__ __forceinline__ ull pack2(float lo, float hi) {
    ull r;
    asm("mov.b64 %0, {%1, %2};" : "=l"(r) : "f"(lo), "f"(hi));
    return r;
}
__device__ __forceinline__ float2 unpack2(ull v) {
    float2 f;
    asm("mov.b64 {%0, %1}, %2;" : "=f"(f.x), "=f"(f.y) : "l"(v));
    return f;
}
__device__ __forceinline__ float sigmoidf_(float v) {
    return 1.f / (1.f + expf(-v));
}
__device__ __forceinline__ void cp_async16(void* smem, const void* g) {
    uint32_t s = (uint32_t)__cvta_generic_to_shared(smem);
    asm volatile("cp.async.cg.shared.global [%0], [%1], 16;" :: "r"(s), "l"(g));
}
__device__ __forceinline__ float to_tf32(float x) {
    uint32_t r;
    asm("cvt.rna.tf32.f32 %0, %1;" : "=r"(r) : "f"(x));
    return __uint_as_float(r);
}
__device__ __forceinline__ void mma_tf32(
    float& d0, float& d1, float& d2, float& d3,
    uint32_t a0, uint32_t a1, uint32_t a2, uint32_t a3,
    uint32_t b0, uint32_t b1)
{
    asm volatile(
        "mma.sync.aligned.m16n8k8.row.col.f32.tf32.tf32.f32 "
        "{%0,%1,%2,%3}, {%4,%5,%6,%7}, {%8,%9}, {%0,%1,%2,%3};"
        : "+f"(d0), "+f"(d1), "+f"(d2), "+f"(d3)
        : "r"(a0), "r"(a1), "r"(a2), "r"(a3), "r"(b0), "r"(b1));
}
#define F2U(x) __float_as_uint(x)

// ---------------------------------------------------------------------------
// Kernel 0a: weight transforms. Deform rows channel-permuted by
// rho(c) = (c%4)*4 + c/4 (involution) to make the gather STS conflict-free.
// ---------------------------------------------------------------------------
__global__ void all_wt_kernel(
    const float* __restrict__ rw,
    const float* __restrict__ mw,
    float* __restrict__ wt, float* __restrict__ mwt)
{
    int i = blockIdx.x * 256 + threadIdx.x;
    if (i < 36864) {
        int o = i & 63;
        int r = i >> 6;
        int crow = r & 15;
        int c = (crow & 3) * 4 + (crow >> 2);   // rho^{-1} == rho
        int r2 = r >> 4;
        int k = r2 % 9, g = r2 / 9;
        wt[i] = to_tf32(rw[(o * 64 + g * 16 + c) * 9 + k]);
    } else if (i < 64512) {
        int i3 = i - 36864;
        int o = i3 % 48;
        int r = i3 / 48;
        int c = r & 7;
        int r2 = r >> 3;
        int chunk = r2 / 9, t = r2 % 9;
        int ic = chunk * 8 + c;
        float v = (o < 36) ? mw[o * 576 + ic * 9 + t] : 0.f;
        mwt[i3] = to_tf32(v);
    }
}

// ---------------------------------------------------------------------------
// Kernel 0b: NCHW -> group-split transpose: [b][64][HW] -> [b*4+g][HW][16]
// ---------------------------------------------------------------------------
__global__ __launch_bounds__(256) void gsplit_kernel(
    const float* __restrict__ in, float* __restrict__ outp)
{
    __shared__ float t[32][33];
    const int tx = threadIdx.x & 31, ty = threadIdx.x >> 5;
    const int p0 = blockIdx.x * 32;
    const int c0 = blockIdx.y * 32;
    const int b  = blockIdx.z;
#pragma unroll
    for (int j = 0; j < 4; j++) {
        int c = c0 + ty + j * 8;
        t[ty + j * 8][tx] = in[((size_t)(b * Cc + c)) * HW + p0 + tx];
    }
    __syncthreads();
#pragma unroll
    for (int j = 0; j < 4; j++) {
        int p = p0 + ty + j * 8;
        int c = c0 + tx;
        int g = c >> 4, ci = c & 15;
        outp[((size_t)(b * 4 + g) * HW + p) * 16 + ci] = t[tx][ty + j * 8];
    }
}

// ---------------------------------------------------------------------------
// Conv bodies for the über kernel (shared SMEM union: 6336 floats)
// ---------------------------------------------------------------------------
__device__ __forceinline__ void offset_conv_body(
    float* sbuf,
    const float* __restrict__ wr, const float* __restrict__ src,
    const float* __restrict__ ow, const float* __restrict__ ob,
    float* __restrict__ out_off, int xb, int yb, int g, int b)
{
    float* s_in = sbuf;          // 4896
    float* s_w  = sbuf + 4896;   // 1440

    const int tid = threadIdx.x;
    const int tx = tid & 31, ty = tid >> 5;
    const int x0 = xb * 32, y0 = yb * 16;

    ull acc[2][9];
#pragma unroll
    for (int p = 0; p < 2; p++)
#pragma unroll
        for (int j = 0; j < 9; j++) acc[p][j] = 0ull;

#pragma unroll 1
    for (int chunk = 0; chunk < 4; chunk++) {
        const float* base = (chunk < 2 ? wr : src)
                          + ((size_t)(b * Cc + g * Cgc + (chunk & 1) * 8)) * HW;
        for (int i = tid; i < 4896; i += 256) {
            int c = i / 612, r = i % 612;
            int iy = r / 34, ix = r % 34;
            int gy = y0 - 1 + iy, gx = x0 - 1 + ix;
            float v = 0.f;
            if (gy >= 0 && gy < Hc && gx >= 0 && gx < Wc)
                v = base[(size_t)c * HW + gy * Wc + gx];
            s_in[i] = v;
        }
        for (int i = tid; i < 1440; i += 256) {
            int o = i % 20;
            int ck = i / 20;
            int k = ck % 9, c = ck / 9;
            s_w[i] = (o < 18) ? ow[(o * 32 + chunk * 8 + c) * 9 + k] : 0.f;
        }
        __syncthreads();

#pragma unroll 2
        for (int c = 0; c < 8; c++) {
#pragma unroll
            for (int t = 0; t < 9; t++) {
                const int kh = t / 3, kw = t % 3;
                const float* wrow = &s_w[(c * 9 + t) * 20];
                ulonglong2 l0 = *(const ulonglong2*)(wrow);
                ulonglong2 l1 = *(const ulonglong2*)(wrow + 4);
                ulonglong2 l2 = *(const ulonglong2*)(wrow + 8);
                ulonglong2 l3 = *(const ulonglong2*)(wrow + 12);
                ull w8 = *(const ull*)(wrow + 16);
#pragma unroll
                for (int p = 0; p < 2; p++) {
                    float v = s_in[c * 612 + (ty + p * 8 + kh) * 34 + tx + kw];
                    ull vv = pack2(v, v);
                    acc[p][0] = ffma2(vv, l0.x, acc[p][0]);
                    acc[p][1] = ffma2(vv, l0.y, acc[p][1]);
                    acc[p][2] = ffma2(vv, l1.x, acc[p][2]);
                    acc[p][3] = ffma2(vv, l1.y, acc[p][3]);
                    acc[p][4] = ffma2(vv, l2.x, acc[p][4]);
                    acc[p][5] = ffma2(vv, l2.y, acc[p][5]);
                    acc[p][6] = ffma2(vv, l3.x, acc[p][6]);
                    acc[p][7] = ffma2(vv, l3.y, acc[p][7]);
                    acc[p][8] = ffma2(vv, w8,  acc[p][8]);
                }
            }
        }
        __syncthreads();
    }

    const int x = x0 + tx;
#pragma unroll
    for (int p = 0; p < 2; p++) {
        int y = y0 + ty + p * 8;
#pragma unroll
        for (int j = 0; j < 9; j++) {
            float2 f = unpack2(acc[p][j]);
            int o0 = 2 * j, o1 = 2 * j + 1;
            float v0 = 100.f * sigmoidf_(f.x + ob[o0]) - 50.f;
            float v1 = 100.f * sigmoidf_(f.y + ob[o1]) - 50.f;
            out_off[((size_t)(b * 72 + g * 18 + o0) * Hc + y) * Wc + x] = v0;
            out_off[((size_t)(b * 72 + g * 18 + o1) * Hc + y) * Wc + x] = v1;
        }
    }
}

__device__ __forceinline__ void mod_conv_mma_body(
    float* sbuf,
    const float* __restrict__ wr,
    const float* __restrict__ gw, const float* __restrict__ mb,
    float* __restrict__ modout, int xb, int yb, int b)
{
    float* s_t = sbuf;           // 2720
    float* s_a = sbuf + 2720;    // 3456

    const int tid = threadIdx.x;
    const int warp = tid >> 5, lane = tid & 31;
    const int lr = lane >> 2, lc = lane & 3;
    const int x0 = xb * 32, y0 = yb * 8;

    float d[3][4][4];
#pragma unroll
    for (int mt = 0; mt < 3; mt++)
#pragma unroll
        for (int nt = 0; nt < 4; nt++)
#pragma unroll
            for (int j = 0; j < 4; j++) d[mt][nt][j] = 0.f;

#pragma unroll 1
    for (int chunk = 0; chunk < 8; chunk++) {
        for (int i = tid * 4; i < 3456; i += 1024)
            cp_async16(&s_a[i], &gw[chunk * 3456 + i]);
        asm volatile("cp.async.commit_group;" ::: "memory");

        const float* base = wr + ((size_t)(b * Cc + chunk * 8)) * HW;
        for (int i = tid; i < 2720; i += 256) {
            int c = i / 340, r = i % 340;
            int iy = r / 34, ix = r % 34;
            int gy = y0 - 1 + iy, gx = x0 - 1 + ix;
            float v = 0.f;
            if (gy >= 0 && gy < Hc && gx >= 0 && gx < Wc)
                v = base[(size_t)c * HW + gy * Wc + gx];
            s_t[i] = to_tf32(v);
        }
        asm volatile("cp.async.wait_group 0;" ::: "memory");
        __syncthreads();

#pragma unroll 1
        for (int t = 0; t < 9; t++) {
            const int kh = t / 3, kw = t % 3;
            const int bb = (warp + kh) * 34 + kw + lr;
            float b0[4], b1[4];
#pragma unroll
            for (int nt = 0; nt < 4; nt++) {
                int a = bb + nt * 8;
                b0[nt] = s_t[lc * 340 + a];
                b1[nt] = s_t[(lc + 4) * 340 + a];
            }
            const float* Aw = &s_a[t * 8 * 48];
#pragma unroll
            for (int mt = 0; mt < 3; mt++) {
                int m = mt * 16 + lr;
                uint32_t a0 = F2U(Aw[lc * 48 + m]);
                uint32_t a1 = F2U(Aw[lc * 48 + m + 8]);
                uint32_t a2 = F2U(Aw[(lc + 4) * 48 + m]);
                uint32_t a3 = F2U(Aw[(lc + 4) * 48 + m + 8]);
#pragma unroll
                for (int nt = 0; nt < 4; nt++) {
                    mma_tf32(d[mt][nt][0], d[mt][nt][1], d[mt][nt][2], d[mt][nt][3],
                             a0, a1, a2, a3, F2U(b0[nt]), F2U(b1[nt]));
                }
            }
        }
        __syncthreads();
    }

    const int yg = y0 + warp;
#pragma unroll
    for (int mt = 0; mt < 3; mt++) {
#pragma unroll
        for (int nt = 0; nt < 4; nt++) {
            int xg = x0 + nt * 8 + 2 * lc;
            int o = mt * 16 + lr;
            if (o < 36) {
                float v0 = 2.f * sigmoidf_(d[mt][nt][0] + mb[o]);
                float v1 = 2.f * sigmoidf_(d[mt][nt][1] + mb[o]);
                *(float2*)&modout[((size_t)(b * 36 + o)) * HW + yg * Wc + xg]
                    = make_float2(v0, v1);
            }
            int o2 = mt * 16 + lr + 8;
            if (o2 < 36) {
                float v0 = 2.f * sigmoidf_(d[mt][nt][2] + mb[o2]);
                float v1 = 2.f * sigmoidf_(d[mt][nt][3] + mb[o2]);
                *(float2*)&modout[((size_t)(b * 36 + o2)) * HW + yg * Wc + xg]
                    = make_float2(v0, v1);
            }
        }
    }
}

// ---------------------------------------------------------------------------
// Kernel 1+2: über conv — 864 CTAs interleaved 2:1 offset(FFMA2):mod(MMA).
// ---------------------------------------------------------------------------
__global__ __launch_bounds__(256, 2) void uber_conv_kernel(
    const float* __restrict__ wr, const float* __restrict__ src,
    const float* __restrict__ ow, const float* __restrict__ ob,
    const float* __restrict__ mgw, const float* __restrict__ mb,
    float* __restrict__ out_off, float* __restrict__ modout)
{
    __shared__ float sbuf[6336];
    const int i = blockIdx.x;
    const int r = i % 3;
    if (r < 2) {
        int idx = (i / 3) * 2 + r;
        int xb = idx % 6;
        int yb = (idx / 6) % 12;
        int zb = idx / 72;
        offset_conv_body(sbuf, wr, src, ow, ob, out_off, xb, yb, zb & 3, zb >> 2);
    } else {
        int idx = i / 3;
        int xb = idx % 6;
        int yb = (idx / 6) % 24;
        int b = idx / 144;
        mod_conv_mma_body(sbuf, wr, mgw, mb, modout, xb, yb, b);
    }
}

// ---------------------------------------------------------------------------
// Kernel 3: FUSED deform — 4 lanes/pixel gather with channel-permuted
// (conflict-free) STS, prefetched offsets, tf32 MMA.
// ---------------------------------------------------------------------------
__global__ __launch_bounds__(256, 2) void deform_fused_kernel(
    const float* __restrict__ gsp,
    const float* __restrict__ off,
    const float* __restrict__ mod,
    const float* __restrict__ gwt,
    float* __restrict__ out_x)
{
    __shared__ float s_val[2][16 * VPAD];
    __shared__ float s_wk[2][16 * 64];
    __shared__ float s_off[2][3 * 256];

    const int tid = threadIdx.x;
    const int warp = tid >> 5, lane = tid & 31;
    const int px8 = lane >> 2;          // pixel within 8-px step
    const int qq = lane & 3;            // channel quad
    const int blk = blockIdx.x;
    const int b = blk / (HW / 256);
    const int ploc0 = (blk % (HW / 256)) * 256;

    const int wo = warp >> 1;
    const int wn = warp & 1;
    const int lr = lane >> 2;
    const int lc = lane & 3;

    auto stage_off = [&](int i) {
        const int g = i / 9, k = i % 9;
        const int sec = tid >> 6;
        const int t4 = (tid & 63) * 4;
        if (sec == 0) {
            cp_async16(&s_off[i & 1][t4],
                       off + (size_t)(b * 72 + g * 18 + 2 * k) * HW + ploc0 + t4);
        } else if (sec == 1) {
            cp_async16(&s_off[i & 1][256 + t4],
                       off + (size_t)(b * 72 + g * 18 + 2 * k + 1) * HW + ploc0 + t4);
        } else if (sec == 2) {
            cp_async16(&s_off[i & 1][512 + t4],
                       mod + (size_t)(b * 36 + g * 9 + k) * HW + ploc0 + t4);
        }
    };

    auto stage_w = [&](int i) {
        int flat = tid * 4;
        int c = flat >> 6, o = flat & 63;
        cp_async16(&s_wk[i & 1][c * 64 + o], &gwt[(i * 16 + c) * 64 + o]);
    };

    auto gather = [&](int i) {
        const int buf = i & 1;
        const int g = i / 9, k = i % 9;
        const int kh = k / 3, kw = k % 3;
        const float* gplane = gsp + (size_t)(b * 4 + g) * HW * 16 + qq * 4;
        const float* so = s_off[buf];
        float* sv = s_val[buf];

#pragma unroll
        for (int s = 0; s < 4; s++) {
            const int pl = warp * 32 + s * 8 + px8;
            const int p = ploc0 + pl;
            const int yy = p / Wc, xx = p % Wc;
            float oy = so[pl];
            float ox = so[256 + pl];
            float m  = so[512 + pl];

            float py = oy + (float)(kh + yy - 1);
            float pxf = ox + (float)(kw + xx - 1);
            float fy = floorf(py), fx = floorf(pxf);
            float ly = py - fy, lx = pxf - fx;
            int y0 = (int)fy, x0 = (int)fx;

            float vy0 = (y0 >= 0 && y0 < Hc) ? 1.f : 0.f;
            float vy1 = (y0 >= -1 && y0 <= Hc - 2) ? 1.f : 0.f;
            float vx0 = (x0 >= 0 && x0 < Wc) ? 1.f : 0.f;
            float vx1 = (x0 >= -1 && x0 <= Wc - 2) ? 1.f : 0.f;

            int ry0 = min(max(y0, 0), Hc - 1);
            int ry1 = min(max(y0 + 1, 0), Hc - 1);
            int cx0 = min(max(x0, 0), Wc - 1);
            int cx1 = min(max(x0 + 1, 0), Wc - 1);

            float w00 = (1.f - ly) * (1.f - lx) * m * vy0 * vx0;
            float w01 = (1.f - ly) * lx * m * vy0 * vx1;
            float w10 = ly * (1.f - lx) * m * vy1 * vx0;
            float w11 = ly * lx * m * vy1 * vx1;

            float4 c00 = __ldg((const float4*)(gplane + ((size_t)(ry0 * Wc + cx0)) * 16));
            float4 c01 = __ldg((const float4*)(gplane + ((size_t)(ry0 * Wc + cx1)) * 16));
            float4 c10 = __ldg((const float4*)(gplane + ((size_t)(ry1 * Wc + cx0)) * 16));
            float4 c11 = __ldg((const float4*)(gplane + ((size_t)(ry1 * Wc + cx1)) * 16));

            float u0 = w00 * c00.x + w01 * c01.x + w10 * c10.x + w11 * c11.x;
            float u1 = w00 * c00.y + w01 * c01.y + w10 * c10.y + w11 * c11.y;
            float u2 = w00 * c00.z + w01 * c01.z + w10 * c10.z + w11 * c11.z;
            float u3 = w00 * c00.w + w01 * c01.w + w10 * c10.w + w11 * c11.w;

            // channel c = 4*qq + j stored at row rho(c) = 4*j + qq
            // bank = (8*(4j+qq) + pl) % 32 = 8*qq + px8 (+const) -> conflict-free
            sv[(0 * 4 + qq) * VPAD + pl] = to_tf32(u0);
            sv[(1 * 4 + qq) * VPAD + pl] = to_tf32(u1);
            sv[(2 * 4 + qq) * VPAD + pl] = to_tf32(u2);
            sv[(3 * 4 + qq) * VPAD + pl] = to_tf32(u3);
        }
    };

    float d[16][4];
#pragma unroll
    for (int nt = 0; nt < 16; nt++)
#pragma unroll
        for (int j = 0; j < 4; j++) d[nt][j] = 0.f;

    stage_off(0);
    stage_off(1);
    stage_w(0);
    asm volatile("cp.async.commit_group;" ::: "memory");
    asm volatile("cp.async.wait_group 0;" ::: "memory");
    __syncthreads();
    gather(0);

#pragma unroll 1
    for (int i = 0; i < 36; i++) {
        asm volatile("cp.async.wait_group 0;" ::: "memory");
        __syncthreads();
        if (i < 35) {
            stage_w(i + 1);
            if (i < 34) stage_off(i + 2);
            asm volatile("cp.async.commit_group;" ::: "memory");
            gather(i + 1);
        }

        const float* sv = s_val[i & 1];
        const float* wk = s_wk[i & 1];
#pragma unroll
        for (int kc = 0; kc < 2; kc++) {
            const int arow = wo * 16 + lr;
            const int ak = kc * 8 + lc;
            uint32_t a0 = __float_as_uint(wk[ak * 64 + arow]);
            uint32_t a1 = __float_as_uint(wk[ak * 64 + arow + 8]);
            uint32_t a2 = __float_as_uint(wk[(ak + 4) * 64 + arow]);
            uint32_t a3 = __float_as_uint(wk[(ak + 4) * 64 + arow + 8]);
#pragma unroll
            for (int nt = 0; nt < 16; nt++) {
                const int n = wn * 128 + nt * 8 + lr;
                const int bk = kc * 8 + lc;
                uint32_t b0 = __float_as_uint(sv[bk * VPAD + n]);
                uint32_t b1 = __float_as_uint(sv[(bk + 4) * VPAD + n]);
                mma_tf32(d[nt][0], d[nt][1], d[nt][2], d[nt][3],
                         a0, a1, a2, a3, b0, b1);
            }
        }
    }

    const int o0 = wo * 16 + lr;
#pragma unroll
    for (int nt = 0; nt < 16; nt++) {
        const size_t p = (size_t)ploc0 + wn * 128 + nt * 8 + 2 * lc;
        *(float2*)&out_x[((size_t)(b * Cc + o0)) * HW + p]     = make_float2(d[nt][0], d[nt][1]);
        *(float2*)&out_x[((size_t)(b * Cc + o0 + 8)) * HW + p] = make_float2(d[nt][2], d[nt][3]);
    }
}

// ---------------------------------------------------------------------------
extern "C" void kernel_launch(void* const* d_in, const int* in_sizes, int n_in,
                              void* d_out, int out_size)
{
    const float* warp_ref = (const float*)d_in[0];
    const float* source   = (const float*)d_in[1];
    const float* offset_w = (const float*)d_in[2];
    const float* offset_b = (const float*)d_in[3];
    const float* mod_w    = (const float*)d_in[4];
    const float* mod_b    = (const float*)d_in[5];
    const float* reg_w    = (const float*)d_in[6];

    float* out_x   = (float*)d_out;             // [B,64,H,W]
    float* out_off = (float*)d_out + X_ELEMS;   // [B,72,H,W]

    float *mod_scratch, *wt_scratch, *gsp_scratch, *mwt;
    cudaGetSymbolAddress((void**)&mod_scratch, g_modulator);
    cudaGetSymbolAddress((void**)&wt_scratch, g_wt);
    cudaGetSymbolAddress((void**)&gsp_scratch, g_gsplit);
    cudaGetSymbolAddress((void**)&mwt, g_mwt);

    dim3 blk(256);
    all_wt_kernel<<<252, blk>>>(reg_w, mod_w, wt_scratch, mwt);
    gsplit_kernel<<<dim3(HW / 32, 2, Bc), blk>>>(warp_ref, gsp_scratch);
    uber_conv_kernel<<<864, blk>>>(warp_ref, source, offset_w, offset_b,
                                   mwt, mod_b, out_off, mod_scratch);
    deform_fused_kernel<<<dim3(Nsz / 256), blk>>>(gsp_scratch, out_off, mod_scratch, wt_scratch, out_x);
}